// round 1
// baseline (speedup 1.0000x reference)
#include <cuda_runtime.h>

static constexpr int NU = 500000;
static constexpr int NI = 100000;
static constexpr int F  = 300;
static constexpr int D  = 64;
static constexpr int E  = 2000000;
static constexpr int EL = 1000000;

// ---------------- device scratch (static allocation; no cudaMalloc) ----------------
__device__ float g_xi  [NI * D];   // item features after input linear
__device__ float g_xiT [NI * D];   // item features pre-transformed by Wl_iu
__device__ float g_aggu[NU * D];   // per-user aggregation buffer
__device__ float g_aggi[NI * D];   // per-item aggregation buffer
__device__ float g_hu  [NU * D];   // user hidden state (layer outputs, in-place across layers)
__device__ float g_hi  [NI * D];   // item hidden state
__device__ float g_cu  [NU];       // user degree -> reciprocal
__device__ float g_ci  [NI];       // item degree -> reciprocal

// ---------------- helpers ----------------
__device__ __forceinline__ unsigned long long pk2(float a, float b) {
    float2 t = make_float2(a, b);
    return *reinterpret_cast<unsigned long long*>(&t);
}
__device__ __forceinline__ float2 upk(unsigned long long v) {
    return *reinterpret_cast<float2*>(&v);
}
// packed f32x2 FMA: d = a*b + c on both 32-bit halves (2x FFMA throughput on sm_103a)
__device__ __forceinline__ unsigned long long ffma2(unsigned long long a,
                                                    unsigned long long b,
                                                    unsigned long long c) {
    unsigned long long d;
    asm("fma.rn.f32x2 %0, %1, %2, %3;" : "=l"(d) : "l"(a), "l"(b), "l"(c));
    return d;
}
// vector reduction atomic: 4 floats in one RED op
__device__ __forceinline__ void red4(float* p, float4 v) {
    asm volatile("red.global.add.v4.f32 [%0], {%1,%2,%3,%4};"
                 :: "l"(p), "f"(v.x), "f"(v.y), "f"(v.z), "f"(v.w) : "memory");
}

// ---------------- small utility kernels ----------------
__global__ void k_zero_counts() {
    int i = blockIdx.x * blockDim.x + threadIdx.x;
    if (i < NU) g_cu[i] = 0.f;
    if (i < NI) g_ci[i] = 0.f;
}

__global__ void k_count(const int* __restrict__ es, const int* __restrict__ ed) {
    int i = blockIdx.x * blockDim.x + threadIdx.x;
    if (i < E) {
        atomicAdd(&g_cu[es[i]], 1.0f);
        atomicAdd(&g_ci[ed[i]], 1.0f);
    }
}

__global__ void k_recip() {
    int i = blockIdx.x * blockDim.x + threadIdx.x;
    if (i < NU) g_cu[i] = 1.0f / fmaxf(g_cu[i], 1.0f);
    if (i < NI) g_ci[i] = 1.0f / fmaxf(g_ci[i], 1.0f);
}

__global__ void k_zero_agg() {
    int i = blockIdx.x * blockDim.x + threadIdx.x;
    float4 z = make_float4(0.f, 0.f, 0.f, 0.f);
    if (i < NU * D / 4) reinterpret_cast<float4*>(g_aggu)[i] = z;
    if (i < NI * D / 4) reinterpret_cast<float4*>(g_aggi)[i] = z;
}

// ---------------- edge scatter: agg[d[e]] += feat[s[e]] (64 floats / edge) ----------------
__global__ void k_scatter(const float* __restrict__ feat,
                          const int* __restrict__ s,
                          const int* __restrict__ d,
                          float* __restrict__ agg) {
    int i = blockIdx.x * blockDim.x + threadIdx.x;   // E*16 work items
    int e = i >> 4;
    int j = i & 15;
    if (e >= E) return;
    int a = s[e];
    int b = d[e];
    float4 v = *reinterpret_cast<const float4*>(feat + a * 64 + j * 4);
    red4(agg + b * 64 + j * 4, v);
}

// ---------------- item input linear: Y = X[NI,300] @ W[300,64] (+bias on first pass) ----------
// K processed in chunks (kn <= 128) across 3 launches; pass accum=1 to add to existing Y.
__global__ void k_item_lin(const float* __restrict__ X, const float* __restrict__ W,
                           const float* __restrict__ bias, float* __restrict__ Y,
                           int k0, int kn, int accum) {
    __shared__ float Ws[128 * 64];
    __shared__ float Xs[16][132];
    const int tx = threadIdx.x;              // 0..7   (8 cols each)
    const int ty = threadIdx.y;              // 0..15  (row)
    const int tid = ty * 8 + tx;

    for (int idx = tid; idx < kn * 64; idx += 128)
        Ws[idx] = W[(k0 + (idx >> 6)) * 64 + (idx & 63)];

    for (int r0 = blockIdx.x * 16; r0 < NI; r0 += gridDim.x * 16) {
        __syncthreads();
        for (int idx = tid; idx < 16 * kn; idx += 128) {
            int r = idx / kn;
            int c = idx - r * kn;
            Xs[r][c] = X[(r0 + r) * F + k0 + c];
        }
        __syncthreads();

        const int row = r0 + ty;
        unsigned long long c0, c1, c2, c3;
        if (accum) {
            const unsigned long long* yp =
                reinterpret_cast<const unsigned long long*>(Y + row * 64 + tx * 8);
            c0 = yp[0]; c1 = yp[1]; c2 = yp[2]; c3 = yp[3];
        } else {
            const float* bp = bias + tx * 8;
            c0 = pk2(bp[0], bp[1]); c1 = pk2(bp[2], bp[3]);
            c2 = pk2(bp[4], bp[5]); c3 = pk2(bp[6], bp[7]);
        }
        #pragma unroll 4
        for (int k = 0; k < kn; k++) {
            float a = Xs[ty][k];
            unsigned long long a2 = pk2(a, a);
            const ulonglong2* wp = reinterpret_cast<const ulonglong2*>(Ws + k * 64 + tx * 8);
            ulonglong2 wA = wp[0], wB = wp[1];
            c0 = ffma2(a2, wA.x, c0); c1 = ffma2(a2, wA.y, c1);
            c2 = ffma2(a2, wB.x, c2); c3 = ffma2(a2, wB.y, c3);
        }
        unsigned long long* yp = reinterpret_cast<unsigned long long*>(Y + row * 64 + tx * 8);
        yp[0] = c0; yp[1] = c1; yp[2] = c2; yp[3] = c3;
    }
}

// ---------------- Y[N,64] = X[N,64] @ W[64,64] (no bias) ----------------
__global__ void k_gemm64(const float* __restrict__ X, const float* __restrict__ W,
                         float* __restrict__ Y, int N) {
    __shared__ float Ws[4096];
    __shared__ float Xs[16][68];
    const int tx = threadIdx.x, ty = threadIdx.y;
    const int tid = ty * 8 + tx;

    for (int idx = tid; idx < 4096; idx += 128) Ws[idx] = W[idx];

    for (int r0 = blockIdx.x * 16; r0 < N; r0 += gridDim.x * 16) {
        __syncthreads();
        for (int idx = tid; idx < 1024; idx += 128) {
            int r = idx >> 6, c = idx & 63;
            Xs[r][c] = X[(r0 + r) * 64 + c];
        }
        __syncthreads();

        const int row = r0 + ty;
        unsigned long long c0 = 0ull, c1 = 0ull, c2 = 0ull, c3 = 0ull;
        #pragma unroll
        for (int k = 0; k < 64; k++) {
            float a = Xs[ty][k];
            unsigned long long a2 = pk2(a, a);
            const ulonglong2* wp = reinterpret_cast<const ulonglong2*>(Ws + k * 64 + tx * 8);
            ulonglong2 wA = wp[0], wB = wp[1];
            c0 = ffma2(a2, wA.x, c0); c1 = ffma2(a2, wA.y, c1);
            c2 = ffma2(a2, wB.x, c2); c3 = ffma2(a2, wB.y, c3);
        }
        unsigned long long* yp = reinterpret_cast<unsigned long long*>(Y + row * 64 + tx * 8);
        yp[0] = c0; yp[1] = c1; yp[2] = c2; yp[3] = c3;
    }
}

// ---------------- item update: Y = act( (agg*rc) @ Wl + X @ Wr + b ) ----------------
__global__ void k_node_i(const float* __restrict__ agg, const float* __restrict__ rc,
                         const float* __restrict__ X,
                         const float* __restrict__ Wl, const float* __restrict__ Wr,
                         const float* __restrict__ bias, float* __restrict__ Y,
                         int doRelu, int N) {
    __shared__ float Wls[4096];
    __shared__ float Wrs[4096];
    __shared__ float As[16][68];
    __shared__ float Xs[16][68];
    const int tx = threadIdx.x, ty = threadIdx.y;
    const int tid = ty * 8 + tx;

    for (int idx = tid; idx < 4096; idx += 128) { Wls[idx] = Wl[idx]; Wrs[idx] = Wr[idx]; }

    for (int r0 = blockIdx.x * 16; r0 < N; r0 += gridDim.x * 16) {
        __syncthreads();
        for (int idx = tid; idx < 1024; idx += 128) {
            int r = idx >> 6, c = idx & 63;
            int row = r0 + r;
            As[r][c] = agg[row * 64 + c];
            Xs[r][c] = X[row * 64 + c];
        }
        __syncthreads();

        const int row = r0 + ty;
        unsigned long long a0 = 0ull, a1 = 0ull, a2c = 0ull, a3 = 0ull;   // agg@Wl
        unsigned long long x0 = 0ull, x1 = 0ull, x2c = 0ull, x3 = 0ull;   // X@Wr
        #pragma unroll
        for (int k = 0; k < 64; k++) {
            float av = As[ty][k];
            float xv = Xs[ty][k];
            unsigned long long ap = pk2(av, av);
            unsigned long long xp = pk2(xv, xv);
            const ulonglong2* wlp = reinterpret_cast<const ulonglong2*>(Wls + k * 64 + tx * 8);
            const ulonglong2* wrp = reinterpret_cast<const ulonglong2*>(Wrs + k * 64 + tx * 8);
            ulonglong2 wlA = wlp[0], wlB = wlp[1];
            ulonglong2 wrA = wrp[0], wrB = wrp[1];
            a0 = ffma2(ap, wlA.x, a0); a1  = ffma2(ap, wlA.y, a1);
            a2c = ffma2(ap, wlB.x, a2c); a3 = ffma2(ap, wlB.y, a3);
            x0 = ffma2(xp, wrA.x, x0); x1  = ffma2(xp, wrA.y, x1);
            x2c = ffma2(xp, wrB.x, x2c); x3 = ffma2(xp, wrB.y, x3);
        }
        const float rcv = rc[row];
        const float* bp = bias + tx * 8;
        float2 A0 = upk(a0), A1 = upk(a1), A2 = upk(a2c), A3 = upk(a3);
        float2 X0 = upk(x0), X1 = upk(x1), X2 = upk(x2c), X3 = upk(x3);
        float y[8];
        y[0] = bp[0] + rcv * A0.x + X0.x;  y[1] = bp[1] + rcv * A0.y + X0.y;
        y[2] = bp[2] + rcv * A1.x + X1.x;  y[3] = bp[3] + rcv * A1.y + X1.y;
        y[4] = bp[4] + rcv * A2.x + X2.x;  y[5] = bp[5] + rcv * A2.y + X2.y;
        y[6] = bp[6] + rcv * A3.x + X3.x;  y[7] = bp[7] + rcv * A3.y + X3.y;
        if (doRelu) {
            #pragma unroll
            for (int t = 0; t < 8; t++) y[t] = fmaxf(y[t], 0.f);
        }
        float4* yp = reinterpret_cast<float4*>(Y + row * 64 + tx * 8);
        yp[0] = make_float4(y[0], y[1], y[2], y[3]);
        yp[1] = make_float4(y[4], y[5], y[6], y[7]);
    }
}

// ---------------- user update: Y = act( agg*rc + X @ Wr + b ) (agg already Wl-transformed) ----
__global__ void k_node_u(const float* __restrict__ agg, const float* __restrict__ rc,
                         const float* __restrict__ X, const float* __restrict__ Wr,
                         const float* __restrict__ bias, float* __restrict__ Y,
                         int doRelu, int N) {
    __shared__ float Ws[4096];
    __shared__ float Xs[16][68];
    const int tx = threadIdx.x, ty = threadIdx.y;
    const int tid = ty * 8 + tx;

    for (int idx = tid; idx < 4096; idx += 128) Ws[idx] = Wr[idx];

    for (int r0 = blockIdx.x * 16; r0 < N; r0 += gridDim.x * 16) {
        __syncthreads();
        for (int idx = tid; idx < 1024; idx += 128) {
            int r = idx >> 6, c = idx & 63;
            Xs[r][c] = X[(r0 + r) * 64 + c];
        }
        __syncthreads();

        const int row = r0 + ty;
        const float rcv = rc[row];
        const float4* ap = reinterpret_cast<const float4*>(agg + row * 64 + tx * 8);
        float4 A0 = ap[0], A1 = ap[1];
        const float* bp = bias + tx * 8;
        unsigned long long c0 = pk2(bp[0] + rcv * A0.x, bp[1] + rcv * A0.y);
        unsigned long long c1 = pk2(bp[2] + rcv * A0.z, bp[3] + rcv * A0.w);
        unsigned long long c2 = pk2(bp[4] + rcv * A1.x, bp[5] + rcv * A1.y);
        unsigned long long c3 = pk2(bp[6] + rcv * A1.z, bp[7] + rcv * A1.w);
        #pragma unroll
        for (int k = 0; k < 64; k++) {
            float a = Xs[ty][k];
            unsigned long long a2 = pk2(a, a);
            const ulonglong2* wp = reinterpret_cast<const ulonglong2*>(Ws + k * 64 + tx * 8);
            ulonglong2 wA = wp[0], wB = wp[1];
            c0 = ffma2(a2, wA.x, c0); c1 = ffma2(a2, wA.y, c1);
            c2 = ffma2(a2, wB.x, c2); c3 = ffma2(a2, wB.y, c3);
        }
        float2 r0p = upk(c0), r1p = upk(c1), r2p = upk(c2), r3p = upk(c3);
        float y[8] = { r0p.x, r0p.y, r1p.x, r1p.y, r2p.x, r2p.y, r3p.x, r3p.y };
        if (doRelu) {
            #pragma unroll
            for (int t = 0; t < 8; t++) y[t] = fmaxf(y[t], 0.f);
        }
        float4* yp = reinterpret_cast<float4*>(Y + row * 64 + tx * 8);
        yp[0] = make_float4(y[0], y[1], y[2], y[3]);
        yp[1] = make_float4(y[4], y[5], y[6], y[7]);
    }
}

// ---------------- predictor: out[e] = dot(hu[ls[e]], hi[ld[e]]) ----------------
__global__ void k_dot(const float* __restrict__ hu, const float* __restrict__ hi,
                      const int* __restrict__ ls, const int* __restrict__ ld,
                      float* __restrict__ out) {
    int i = blockIdx.x * blockDim.x + threadIdx.x;  // EL*8 work items
    int e = i >> 3;
    int j = i & 7;
    if (e >= EL) return;
    int u = ls[e];
    int v = ld[e];
    const float4* pa = reinterpret_cast<const float4*>(hu + u * 64 + j * 8);
    const float4* pb = reinterpret_cast<const float4*>(hi + v * 64 + j * 8);
    float4 a0 = pa[0], a1 = pa[1], b0 = pb[0], b1 = pb[1];
    float s = a0.x * b0.x + a0.y * b0.y + a0.z * b0.z + a0.w * b0.w
            + a1.x * b1.x + a1.y * b1.y + a1.z * b1.z + a1.w * b1.w;
    s += __shfl_down_sync(0xffffffffu, s, 4, 8);
    s += __shfl_down_sync(0xffffffffu, s, 2, 8);
    s += __shfl_down_sync(0xffffffffu, s, 1, 8);
    if (j == 0) out[e] = s;
}

// ---------------- launch ----------------
extern "C" void kernel_launch(void* const* d_in, const int* in_sizes, int n_in,
                              void* d_out, int out_size) {
    const float* user_emb = (const float*)d_in[0];   // [NU,64] (user_node_id is arange -> identity)
    const float* item_x   = (const float*)d_in[1];   // [NI,300]
    const float* Wlin     = (const float*)d_in[2];   // [300,64]
    const float* blin     = (const float*)d_in[3];
    const float* Wl1_ui   = (const float*)d_in[4];
    const float* Wr1_ui   = (const float*)d_in[5];
    const float* b1_ui    = (const float*)d_in[6];
    const float* Wl1_iu   = (const float*)d_in[7];
    const float* Wr1_iu   = (const float*)d_in[8];
    const float* b1_iu    = (const float*)d_in[9];
    const float* Wl2_ui   = (const float*)d_in[10];
    const float* Wr2_ui   = (const float*)d_in[11];
    const float* b2_ui    = (const float*)d_in[12];
    const float* Wl2_iu   = (const float*)d_in[13];
    const float* Wr2_iu   = (const float*)d_in[14];
    const float* b2_iu    = (const float*)d_in[15];
    // d_in[16] = user_node_id (identity, unused)
    const int* es   = (const int*)d_in[17];
    const int* ed   = (const int*)d_in[18];
    const int* ls   = (const int*)d_in[19];
    const int* ldst = (const int*)d_in[20];
    float* out = (float*)d_out;

    float *aggu, *aggi, *xi, *xiT, *hu, *hi, *cu, *ci;
    cudaGetSymbolAddress((void**)&aggu, g_aggu);
    cudaGetSymbolAddress((void**)&aggi, g_aggi);
    cudaGetSymbolAddress((void**)&xi,   g_xi);
    cudaGetSymbolAddress((void**)&xiT,  g_xiT);
    cudaGetSymbolAddress((void**)&hu,   g_hu);
    cudaGetSymbolAddress((void**)&hi,   g_hi);
    cudaGetSymbolAddress((void**)&cu,   g_cu);
    cudaGetSymbolAddress((void**)&ci,   g_ci);

    const dim3 gb(8, 16);          // 128 threads for GEMM-style kernels
    const int GG = 1024;           // grid-stride block count (W staged once per block)
    const int scatterBlocks = (E * 16) / 256;     // exact: 125000
    const int dotBlocks     = (EL * 8) / 256;     // exact: 31250
    const int zeroBlocks    = (NU * D / 4 + 255) / 256;

    // degrees -> reciprocals (shared by both layers)
    k_zero_counts<<<(NU + 255) / 256, 256>>>();
    k_count<<<(E + 255) / 256, 256>>>(es, ed);
    k_recip<<<(NU + 255) / 256, 256>>>();

    // item input linear (K split 128/128/44)
    k_item_lin<<<GG, gb>>>(item_x, Wlin, blin, xi, 0,   128, 0);
    k_item_lin<<<GG, gb>>>(item_x, Wlin, blin, xi, 128, 128, 1);
    k_item_lin<<<GG, gb>>>(item_x, Wlin, blin, xi, 256, 44,  1);

    // ---- layer 1 ----
    k_zero_agg<<<zeroBlocks, 256>>>();
    k_scatter<<<scatterBlocks, 256>>>(user_emb, es, ed, aggi);     // user -> item (raw)
    k_gemm64<<<GG, gb>>>(xi, Wl1_iu, xiT, NI);                     // pre-transform item feats
    k_scatter<<<scatterBlocks, 256>>>(xiT, ed, es, aggu);          // item -> user (transformed)
    k_node_i<<<GG, gb>>>(aggi, ci, xi, Wl1_ui, Wr1_ui, b1_ui, hi, 1, NI);
    k_node_u<<<GG, gb>>>(aggu, cu, user_emb, Wr1_iu, b1_iu, hu, 1, NU);

    // ---- layer 2 ----
    k_zero_agg<<<zeroBlocks, 256>>>();
    k_scatter<<<scatterBlocks, 256>>>(hu, es, ed, aggi);
    k_gemm64<<<GG, gb>>>(hi, Wl2_iu, xiT, NI);
    k_scatter<<<scatterBlocks, 256>>>(xiT, ed, es, aggu);
    k_node_i<<<GG, gb>>>(aggi, ci, hi, Wl2_ui, Wr2_ui, b2_ui, hi, 0, NI);
    k_node_u<<<GG, gb>>>(aggu, cu, hu, Wr2_iu, b2_iu, hu, 0, NU);

    // predictor
    k_dot<<<dotBlocks, 256>>>(hu, hi, ls, ldst, out);
}

// round 2
// speedup vs baseline: 1.6594x; 1.6594x over previous
#include <cuda_runtime.h>

static constexpr int NU = 500000;
static constexpr int NI = 100000;
static constexpr int F  = 300;
static constexpr int D  = 64;
static constexpr int E  = 2000000;
static constexpr int EL = 1000000;

// ---------------- device scratch ----------------
__device__ float g_xi  [NI * D];
__device__ float g_xiT [NI * D];
__device__ float g_aggu[NU * D];
__device__ float g_aggi[NI * D];
__device__ float g_hu  [NU * D];
__device__ float g_hi  [NI * D];
__device__ float g_cu  [NU];
__device__ float g_ci  [NI];

// ---------------- helpers ----------------
__device__ __forceinline__ unsigned long long pk2(float a, float b) {
    float2 t = make_float2(a, b);
    return *reinterpret_cast<unsigned long long*>(&t);
}
__device__ __forceinline__ float2 upk(unsigned long long v) {
    return *reinterpret_cast<float2*>(&v);
}
__device__ __forceinline__ unsigned long long ffma2(unsigned long long a,
                                                    unsigned long long b,
                                                    unsigned long long c) {
    unsigned long long d;
    asm("fma.rn.f32x2 %0, %1, %2, %3;" : "=l"(d) : "l"(a), "l"(b), "l"(c));
    return d;
}
__device__ __forceinline__ void red4(float* p, float4 v) {
    asm volatile("red.global.add.v4.f32 [%0], {%1,%2,%3,%4};"
                 :: "l"(p), "f"(v.x), "f"(v.y), "f"(v.z), "f"(v.w) : "memory");
}

// ---------------- utility kernels ----------------
__global__ void k_zero_counts() {
    int i = blockIdx.x * blockDim.x + threadIdx.x;
    if (i < NU) g_cu[i] = 0.f;
    if (i < NI) g_ci[i] = 0.f;
}
__global__ void k_count(const int* __restrict__ es, const int* __restrict__ ed) {
    int i = blockIdx.x * blockDim.x + threadIdx.x;
    if (i < E) {
        atomicAdd(&g_cu[es[i]], 1.0f);
        atomicAdd(&g_ci[ed[i]], 1.0f);
    }
}
__global__ void k_recip() {
    int i = blockIdx.x * blockDim.x + threadIdx.x;
    if (i < NU) g_cu[i] = 1.0f / fmaxf(g_cu[i], 1.0f);
    if (i < NI) g_ci[i] = 1.0f / fmaxf(g_ci[i], 1.0f);
}
__global__ void k_zero_agg() {
    int i = blockIdx.x * blockDim.x + threadIdx.x;
    float4 z = make_float4(0.f, 0.f, 0.f, 0.f);
    if (i < NU * D / 4) reinterpret_cast<float4*>(g_aggu)[i] = z;
    if (i < NI * D / 4) reinterpret_cast<float4*>(g_aggi)[i] = z;
}

// ---------------- edge scatter: agg[d[e]] += feat[s[e]] ----------------
__global__ void k_scatter(const float* __restrict__ feat,
                          const int* __restrict__ s,
                          const int* __restrict__ d,
                          float* __restrict__ agg) {
    int i = blockIdx.x * blockDim.x + threadIdx.x;   // E*8 work items
    int e = i >> 3;
    int j = i & 7;
    if (e >= E) return;
    int a = s[e];
    int b = d[e];
    const float4* fp = reinterpret_cast<const float4*>(feat + a * 64 + j * 8);
    float4 v0 = fp[0], v1 = fp[1];
    red4(agg + b * 64 + j * 8,     v0);
    red4(agg + b * 64 + j * 8 + 4, v1);
}

// ============================================================================
// Register-blocked GEMM core: tile = 128 rows x 64 cols, 256 threads.
// Thread computes 4 rows (ty + 32*i) x 8 cols (tx*8..tx*8+7).
// X tile stored as xor-swizzled float4 (stride 16 f4, idx c4 ^ (row&15)).
// ============================================================================

// Generic: Y = relu?( bias? + rcAdd*aggAdd? + (rcA*Xa)@Wa [+ Xb@Wb] )
__global__ __launch_bounds__(256) void k_mm(
    int N,
    const float* __restrict__ Xa, const float* __restrict__ rcA,
    const float* __restrict__ Wa,
    const float* __restrict__ Xb, const float* __restrict__ Wb,
    const float* __restrict__ bias,
    const float* __restrict__ aggAdd, const float* __restrict__ rcAdd,
    int relu, float* __restrict__ Y)
{
    __shared__ float4 Xs[2048];   // 32 KB
    __shared__ float4 Ws[1024];   // 16 KB
    const int tid = threadIdx.x;
    const int tx  = (tid >> 2) & 7;
    const int ty  = (tid >> 5) * 4 + (tid & 3);

    for (int tile = blockIdx.x * 128; tile < N; tile += gridDim.x * 128) {
        // ---- init accumulators ----
        float fa[4][8];
        #pragma unroll
        for (int i = 0; i < 4; i++) {
            #pragma unroll
            for (int t = 0; t < 8; t++) fa[i][t] = 0.f;
        }
        if (bias) {
            #pragma unroll
            for (int i = 0; i < 4; i++) {
                #pragma unroll
                for (int t = 0; t < 8; t++) fa[i][t] = bias[tx * 8 + t];
            }
        }
        if (aggAdd) {
            #pragma unroll
            for (int i = 0; i < 4; i++) {
                int rg = tile + ty + 32 * i;
                if (rg < N) {
                    float rv = rcAdd[rg];
                    const float4* ap = reinterpret_cast<const float4*>(aggAdd + rg * 64 + tx * 8);
                    float4 a0 = ap[0], a1 = ap[1];
                    fa[i][0] += rv * a0.x; fa[i][1] += rv * a0.y;
                    fa[i][2] += rv * a0.z; fa[i][3] += rv * a0.w;
                    fa[i][4] += rv * a1.x; fa[i][5] += rv * a1.y;
                    fa[i][6] += rv * a1.z; fa[i][7] += rv * a1.w;
                }
            }
        }
        unsigned long long acc[4][4];
        #pragma unroll
        for (int i = 0; i < 4; i++) {
            acc[i][0] = pk2(fa[i][0], fa[i][1]); acc[i][1] = pk2(fa[i][2], fa[i][3]);
            acc[i][2] = pk2(fa[i][4], fa[i][5]); acc[i][3] = pk2(fa[i][6], fa[i][7]);
        }

        // ---- up to 2 GEMM passes ----
        #pragma unroll 1
        for (int p = 0; p < 2; p++) {
            const float* X  = p ? Xb : Xa;
            const float* W  = p ? Wb : Wa;
            const float* rc = p ? nullptr : rcA;
            if (!X) break;

            __syncthreads();
            // load W [64][64] into Ws (plain layout, 16 float4 per k-row)
            #pragma unroll
            for (int j = 0; j < 4; j++) {
                int f = tid + j * 256;
                Ws[f] = reinterpret_cast<const float4*>(W)[f];
            }
            // load X tile (swizzled)
            #pragma unroll
            for (int j = 0; j < 8; j++) {
                int f = tid + j * 256;
                int row = f >> 4, c4 = f & 15;
                int rg = tile + row;
                float4 v = make_float4(0.f, 0.f, 0.f, 0.f);
                if (rg < N) {
                    v = reinterpret_cast<const float4*>(X)[rg * 16 + c4];
                    if (rc) { float sc = rc[rg]; v.x *= sc; v.y *= sc; v.z *= sc; v.w *= sc; }
                }
                Xs[row * 16 + (c4 ^ (row & 15))] = v;
            }
            __syncthreads();

            #pragma unroll
            for (int kb = 0; kb < 16; kb++) {
                float4 xv[4];
                #pragma unroll
                for (int i = 0; i < 4; i++) {
                    int r = ty + 32 * i;
                    xv[i] = Xs[r * 16 + (kb ^ (r & 15))];
                }
                #pragma unroll
                for (int q = 0; q < 4; q++) {
                    int k = kb * 4 + q;
                    ulonglong2 wA = *reinterpret_cast<const ulonglong2*>(Ws + k * 16 + tx * 2);
                    ulonglong2 wB = *reinterpret_cast<const ulonglong2*>(Ws + k * 16 + tx * 2 + 1);
                    #pragma unroll
                    for (int i = 0; i < 4; i++) {
                        float a = (q == 0) ? xv[i].x : (q == 1) ? xv[i].y : (q == 2) ? xv[i].z : xv[i].w;
                        unsigned long long a2 = pk2(a, a);
                        acc[i][0] = ffma2(a2, wA.x, acc[i][0]);
                        acc[i][1] = ffma2(a2, wA.y, acc[i][1]);
                        acc[i][2] = ffma2(a2, wB.x, acc[i][2]);
                        acc[i][3] = ffma2(a2, wB.y, acc[i][3]);
                    }
                }
            }
        }

        // ---- store ----
        #pragma unroll
        for (int i = 0; i < 4; i++) {
            int rg = tile + ty + 32 * i;
            if (rg < N) {
                float2 r0 = upk(acc[i][0]), r1 = upk(acc[i][1]);
                float2 r2 = upk(acc[i][2]), r3 = upk(acc[i][3]);
                float y[8] = { r0.x, r0.y, r1.x, r1.y, r2.x, r2.y, r3.x, r3.y };
                if (relu) {
                    #pragma unroll
                    for (int t = 0; t < 8; t++) y[t] = fmaxf(y[t], 0.f);
                }
                float4* yp = reinterpret_cast<float4*>(Y + rg * 64 + tx * 8);
                yp[0] = make_float4(y[0], y[1], y[2], y[3]);
                yp[1] = make_float4(y[4], y[5], y[6], y[7]);
            }
        }
    }
}

// item input linear: Y[NI,64] = X[NI,300] @ W[300,64] + bias (single launch, K-chunked)
__global__ __launch_bounds__(256) void k_lin(
    const float* __restrict__ X, const float* __restrict__ W,
    const float* __restrict__ bias, float* __restrict__ Y)
{
    __shared__ float4 Xs[2048];
    __shared__ float4 Ws[1024];
    const int tid = threadIdx.x;
    const int tx  = (tid >> 2) & 7;
    const int ty  = (tid >> 5) * 4 + (tid & 3);

    for (int tile = blockIdx.x * 128; tile < NI; tile += gridDim.x * 128) {
        unsigned long long acc[4][4];
        {
            const float* bp = bias + tx * 8;
            unsigned long long b0 = pk2(bp[0], bp[1]), b1 = pk2(bp[2], bp[3]);
            unsigned long long b2 = pk2(bp[4], bp[5]), b3 = pk2(bp[6], bp[7]);
            #pragma unroll
            for (int i = 0; i < 4; i++) {
                acc[i][0] = b0; acc[i][1] = b1; acc[i][2] = b2; acc[i][3] = b3;
            }
        }

        #pragma unroll 1
        for (int kc = 0; kc < 5; kc++) {
            const int k0 = kc * 64;
            const int kn = (k0 + 64 <= F) ? 64 : (F - k0);   // 64,64,64,64,44

            __syncthreads();
            #pragma unroll
            for (int j = 0; j < 4; j++) {
                int f = tid + j * 256;
                int k = f >> 4, c4 = f & 15;
                float4 v = make_float4(0.f, 0.f, 0.f, 0.f);
                if (k < kn) v = reinterpret_cast<const float4*>(W + (k0 + k) * 64)[c4];
                Ws[f] = v;
            }
            #pragma unroll
            for (int j = 0; j < 8; j++) {
                int f = tid + j * 256;
                int row = f >> 4, c4 = f & 15;
                int rg = tile + row;
                float4 v = make_float4(0.f, 0.f, 0.f, 0.f);
                if (rg < NI && c4 * 4 < kn)
                    v = *reinterpret_cast<const float4*>(X + rg * F + k0 + c4 * 4);
                Xs[row * 16 + (c4 ^ (row & 15))] = v;
            }
            __syncthreads();

            #pragma unroll
            for (int kb = 0; kb < 16; kb++) {
                float4 xv[4];
                #pragma unroll
                for (int i = 0; i < 4; i++) {
                    int r = ty + 32 * i;
                    xv[i] = Xs[r * 16 + (kb ^ (r & 15))];
                }
                #pragma unroll
                for (int q = 0; q < 4; q++) {
                    int k = kb * 4 + q;
                    ulonglong2 wA = *reinterpret_cast<const ulonglong2*>(Ws + k * 16 + tx * 2);
                    ulonglong2 wB = *reinterpret_cast<const ulonglong2*>(Ws + k * 16 + tx * 2 + 1);
                    #pragma unroll
                    for (int i = 0; i < 4; i++) {
                        float a = (q == 0) ? xv[i].x : (q == 1) ? xv[i].y : (q == 2) ? xv[i].z : xv[i].w;
                        unsigned long long a2 = pk2(a, a);
                        acc[i][0] = ffma2(a2, wA.x, acc[i][0]);
                        acc[i][1] = ffma2(a2, wA.y, acc[i][1]);
                        acc[i][2] = ffma2(a2, wB.x, acc[i][2]);
                        acc[i][3] = ffma2(a2, wB.y, acc[i][3]);
                    }
                }
            }
        }

        #pragma unroll
        for (int i = 0; i < 4; i++) {
            int rg = tile + ty + 32 * i;
            if (rg < NI) {
                float2 r0 = upk(acc[i][0]), r1 = upk(acc[i][1]);
                float2 r2 = upk(acc[i][2]), r3 = upk(acc[i][3]);
                float4* yp = reinterpret_cast<float4*>(Y + rg * 64 + tx * 8);
                yp[0] = make_float4(r0.x, r0.y, r1.x, r1.y);
                yp[1] = make_float4(r2.x, r2.y, r3.x, r3.y);
            }
        }
    }
}

// ---------------- predictor ----------------
__global__ void k_dot(const float* __restrict__ hu, const float* __restrict__ hi,
                      const int* __restrict__ ls, const int* __restrict__ ld,
                      float* __restrict__ out) {
    int i = blockIdx.x * blockDim.x + threadIdx.x;  // EL*8 work items
    int e = i >> 3;
    int j = i & 7;
    if (e >= EL) return;
    int u = ls[e];
    int v = ld[e];
    const float4* pa = reinterpret_cast<const float4*>(hu + u * 64 + j * 8);
    const float4* pb = reinterpret_cast<const float4*>(hi + v * 64 + j * 8);
    float4 a0 = pa[0], a1 = pa[1], b0 = pb[0], b1 = pb[1];
    float s = a0.x * b0.x + a0.y * b0.y + a0.z * b0.z + a0.w * b0.w
            + a1.x * b1.x + a1.y * b1.y + a1.z * b1.z + a1.w * b1.w;
    s += __shfl_down_sync(0xffffffffu, s, 4, 8);
    s += __shfl_down_sync(0xffffffffu, s, 2, 8);
    s += __shfl_down_sync(0xffffffffu, s, 1, 8);
    if (j == 0) out[e] = s;
}

// ---------------- launch ----------------
extern "C" void kernel_launch(void* const* d_in, const int* in_sizes, int n_in,
                              void* d_out, int out_size) {
    const float* user_emb = (const float*)d_in[0];
    const float* item_x   = (const float*)d_in[1];
    const float* Wlin     = (const float*)d_in[2];
    const float* blin     = (const float*)d_in[3];
    const float* Wl1_ui   = (const float*)d_in[4];
    const float* Wr1_ui   = (const float*)d_in[5];
    const float* b1_ui    = (const float*)d_in[6];
    const float* Wl1_iu   = (const float*)d_in[7];
    const float* Wr1_iu   = (const float*)d_in[8];
    const float* b1_iu    = (const float*)d_in[9];
    const float* Wl2_ui   = (const float*)d_in[10];
    const float* Wr2_ui   = (const float*)d_in[11];
    const float* b2_ui    = (const float*)d_in[12];
    const float* Wl2_iu   = (const float*)d_in[13];
    const float* Wr2_iu   = (const float*)d_in[14];
    const float* b2_iu    = (const float*)d_in[15];
    const int* es   = (const int*)d_in[17];
    const int* ed   = (const int*)d_in[18];
    const int* ls   = (const int*)d_in[19];
    const int* ldst = (const int*)d_in[20];
    float* out = (float*)d_out;

    float *aggu, *aggi, *xi, *xiT, *hu, *hi, *cu, *ci;
    cudaGetSymbolAddress((void**)&aggu, g_aggu);
    cudaGetSymbolAddress((void**)&aggi, g_aggi);
    cudaGetSymbolAddress((void**)&xi,   g_xi);
    cudaGetSymbolAddress((void**)&xiT,  g_xiT);
    cudaGetSymbolAddress((void**)&hu,   g_hu);
    cudaGetSymbolAddress((void**)&hi,   g_hi);
    cudaGetSymbolAddress((void**)&cu,   g_cu);
    cudaGetSymbolAddress((void**)&ci,   g_ci);

    const int GMM = 444;                          // 148 SMs x ~3 blocks
    const int scatterBlocks = (E * 8) / 256;      // 62500
    const int dotBlocks     = (EL * 8) / 256;     // 31250
    const int zeroBlocks    = (NU * D / 4 + 255) / 256;

    // degrees -> reciprocals
    k_zero_counts<<<(NU + 255) / 256, 256>>>();
    k_count<<<(E + 255) / 256, 256>>>(es, ed);
    k_recip<<<(NU + 255) / 256, 256>>>();

    // item input linear (single launch)
    k_lin<<<GMM, 256>>>(item_x, Wlin, blin, xi);

    // ---- layer 1 ----
    k_zero_agg<<<zeroBlocks, 256>>>();
    k_scatter<<<scatterBlocks, 256>>>(user_emb, es, ed, aggi);       // user -> item
    k_mm<<<GMM, 256>>>(NI, xi, nullptr, Wl1_iu, nullptr, nullptr,
                       nullptr, nullptr, nullptr, 0, xiT);           // pre-transform items
    k_scatter<<<scatterBlocks, 256>>>(xiT, ed, es, aggu);            // item -> user
    k_mm<<<GMM, 256>>>(NI, aggi, ci, Wl1_ui, xi, Wr1_ui,
                       b1_ui, nullptr, nullptr, 1, hi);              // item update
    k_mm<<<GMM, 256>>>(NU, user_emb, nullptr, Wr1_iu, nullptr, nullptr,
                       b1_iu, aggu, cu, 1, hu);                      // user update

    // ---- layer 2 ----
    k_zero_agg<<<zeroBlocks, 256>>>();
    k_scatter<<<scatterBlocks, 256>>>(hu, es, ed, aggi);
    k_mm<<<GMM, 256>>>(NI, hi, nullptr, Wl2_iu, nullptr, nullptr,
                       nullptr, nullptr, nullptr, 0, xiT);
    k_scatter<<<scatterBlocks, 256>>>(xiT, ed, es, aggu);
    k_mm<<<GMM, 256>>>(NI, aggi, ci, Wl2_ui, hi, Wr2_ui,
                       b2_ui, nullptr, nullptr, 0, hi);
    k_mm<<<GMM, 256>>>(NU, hu, nullptr, Wr2_iu, nullptr, nullptr,
                       b2_iu, aggu, cu, 0, hu);

    // predictor
    k_dot<<<dotBlocks, 256>>>(hu, hi, ls, ldst, out);
}

// round 3
// speedup vs baseline: 3.0522x; 1.8394x over previous
#include <cuda_runtime.h>

static constexpr int NU = 500000;
static constexpr int NI = 100000;
static constexpr int F  = 300;
static constexpr int D  = 64;
static constexpr int E  = 2000000;
static constexpr int EL = 1000000;

// ---------------- device scratch ----------------
__device__ float g_xi  [NI * D];
__device__ float g_xiT [NI * D];
__device__ float g_hu  [NU * D];
__device__ float g_hi  [NI * D];
__device__ int   g_degI[NI];
__device__ int   g_degU[NU];
__device__ int   g_offI[NI + 1];
__device__ int   g_offU[NU + 1];
__device__ int   g_curI[NI];
__device__ int   g_curU[NU];
__device__ int   g_csrI[E];      // grouped by item: stores user ids
__device__ int   g_csrU[E];      // grouped by user: stores item ids
__device__ int   g_bsumI[64];
__device__ int   g_bsumU[256];

// ---------------- helpers ----------------
__device__ __forceinline__ unsigned long long pk2(float a, float b) {
    float2 t = make_float2(a, b);
    return *reinterpret_cast<unsigned long long*>(&t);
}
__device__ __forceinline__ float2 upk(unsigned long long v) {
    return *reinterpret_cast<float2*>(&v);
}
__device__ __forceinline__ unsigned long long ffma2(unsigned long long a,
                                                    unsigned long long b,
                                                    unsigned long long c) {
    unsigned long long d;
    asm("fma.rn.f32x2 %0, %1, %2, %3;" : "=l"(d) : "l"(a), "l"(b), "l"(c));
    return d;
}

// ---------------- CSR build ----------------
__global__ void k_zero_deg() {
    int i = blockIdx.x * blockDim.x + threadIdx.x;
    if (i < NU) { g_degU[i] = 0; g_curU[i] = 0; }
    if (i < NI) { g_degI[i] = 0; g_curI[i] = 0; }
}
__global__ void k_count(const int* __restrict__ es, const int* __restrict__ ed) {
    int i = blockIdx.x * blockDim.x + threadIdx.x;
    if (i < E) {
        atomicAdd(&g_degU[es[i]], 1);
        atomicAdd(&g_degI[ed[i]], 1);
    }
}

// hierarchical exclusive scan: A (per-2048 block), B (scan block sums), C (add offsets)
__global__ void k_scan_a(const int* __restrict__ deg, int n,
                         int* __restrict__ out, int* __restrict__ bsum) {
    __shared__ int ws[8];
    const int t = threadIdx.x;
    const int base = blockIdx.x * 2048 + t * 8;
    int v[8];
    #pragma unroll
    for (int j = 0; j < 8; j++) v[j] = (base + j < n) ? deg[base + j] : 0;
    int s = 0;
    #pragma unroll
    for (int j = 0; j < 8; j++) { int x = v[j]; v[j] = s; s += x; }
    const int lane = t & 31, wid = t >> 5;
    int sx = s;
    #pragma unroll
    for (int o = 1; o < 32; o <<= 1) {
        int y = __shfl_up_sync(0xffffffffu, sx, o);
        if (lane >= o) sx += y;
    }
    if (lane == 31) ws[wid] = sx;
    __syncthreads();
    if (wid == 0 && lane < 8) {
        int b = ws[lane];
        int bx = b;
        #pragma unroll
        for (int o = 1; o < 8; o <<= 1) {
            int y = __shfl_up_sync(0xffu, bx, o);
            if (lane >= o) bx += y;
        }
        ws[lane] = bx - b;
        if (lane == 7) bsum[blockIdx.x] = bx;
    }
    __syncthreads();
    const int off = ws[wid] + (sx - s);
    #pragma unroll
    for (int j = 0; j < 8; j++)
        if (base + j < n) out[base + j] = off + v[j];
}
__global__ void k_scan_b(int* __restrict__ bsum, int nb) {
    __shared__ int sm[256];
    const int t = threadIdx.x;
    int v = (t < nb) ? bsum[t] : 0;
    sm[t] = v;
    __syncthreads();
    for (int o = 1; o < 256; o <<= 1) {
        int y = (t >= o) ? sm[t - o] : 0;
        __syncthreads();
        sm[t] += y;
        __syncthreads();
    }
    if (t < nb) bsum[t] = sm[t] - v;
}
__global__ void k_scan_c(int* __restrict__ out, const int* __restrict__ bsum,
                         int n, int total) {
    int i = blockIdx.x * blockDim.x + threadIdx.x;
    if (i < n) out[i] += bsum[i >> 11];
    if (i == 0) out[n] = total;
}
__global__ void k_fill(const int* __restrict__ es, const int* __restrict__ ed) {
    int e = blockIdx.x * blockDim.x + threadIdx.x;
    if (e < E) {
        int u = es[e], it = ed[e];
        g_csrI[g_offI[it] + atomicAdd(&g_curI[it], 1)] = u;
        g_csrU[g_offU[u] + atomicAdd(&g_curU[u], 1)] = it;
    }
}

// ============================================================================
// GEMM macro-body pieces (tile = 128 rows x 64 cols, 256 threads,
// thread computes 4 rows x 8 cols; Xs xor-swizzled float4).
// ============================================================================
#define GEMM_PASS(ACC)                                                            \
    _Pragma("unroll")                                                             \
    for (int kb = 0; kb < 16; kb++) {                                             \
        float4 xv[4];                                                             \
        _Pragma("unroll")                                                         \
        for (int i = 0; i < 4; i++) {                                             \
            int r = ty + 32 * i;                                                  \
            xv[i] = Xs[r * 16 + (kb ^ (r & 15))];                                 \
        }                                                                         \
        _Pragma("unroll")                                                         \
        for (int q = 0; q < 4; q++) {                                             \
            int k = kb * 4 + q;                                                   \
            ulonglong2 wA = *reinterpret_cast<const ulonglong2*>(Ws + k * 16 + tx * 2);     \
            ulonglong2 wB = *reinterpret_cast<const ulonglong2*>(Ws + k * 16 + tx * 2 + 1); \
            _Pragma("unroll")                                                     \
            for (int i = 0; i < 4; i++) {                                         \
                float a = (q == 0) ? xv[i].x : (q == 1) ? xv[i].y                 \
                        : (q == 2) ? xv[i].z : xv[i].w;                           \
                unsigned long long a2 = pk2(a, a);                                \
                ACC[i][0] = ffma2(a2, wA.x, ACC[i][0]);                           \
                ACC[i][1] = ffma2(a2, wA.y, ACC[i][1]);                           \
                ACC[i][2] = ffma2(a2, wB.x, ACC[i][2]);                           \
                ACC[i][3] = ffma2(a2, wB.y, ACC[i][3]);                           \
            }                                                                     \
        }                                                                         \
    }

// ---------------- simple GEMM: Y[N,64] = X[N,64] @ W[64,64] ----------------
__global__ __launch_bounds__(256) void k_gemm(
    const float* __restrict__ X, const float* __restrict__ W,
    float* __restrict__ Y, int N)
{
    __shared__ float4 Xs[2048];
    __shared__ float4 Ws[1024];
    const int tid = threadIdx.x;
    const int tx  = (tid >> 2) & 7;
    const int ty  = (tid >> 5) * 4 + (tid & 3);

    #pragma unroll
    for (int j = 0; j < 4; j++) Ws[tid + j * 256] = reinterpret_cast<const float4*>(W)[tid + j * 256];

    for (int tile = blockIdx.x * 128; tile < N; tile += gridDim.x * 128) {
        __syncthreads();
        #pragma unroll
        for (int j = 0; j < 8; j++) {
            int f = tid + j * 256;
            int row = f >> 4, c4 = f & 15;
            int rg = tile + row;
            float4 v = make_float4(0.f, 0.f, 0.f, 0.f);
            if (rg < N) v = reinterpret_cast<const float4*>(X)[rg * 16 + c4];
            Xs[row * 16 + (c4 ^ (row & 15))] = v;
        }
        __syncthreads();

        unsigned long long acc[4][4];
        #pragma unroll
        for (int i = 0; i < 4; i++)
            #pragma unroll
            for (int t = 0; t < 4; t++) acc[i][t] = 0ull;

        GEMM_PASS(acc)

        #pragma unroll
        for (int i = 0; i < 4; i++) {
            int rg = tile + ty + 32 * i;
            if (rg < N) {
                float2 r0 = upk(acc[i][0]), r1 = upk(acc[i][1]);
                float2 r2 = upk(acc[i][2]), r3 = upk(acc[i][3]);
                float4* yp = reinterpret_cast<float4*>(Y + rg * 64 + tx * 8);
                yp[0] = make_float4(r0.x, r0.y, r1.x, r1.y);
                yp[1] = make_float4(r2.x, r2.y, r3.x, r3.y);
            }
        }
    }
}

// ---------------- item update: Y = relu?( b + gathermean(srcFeat)@Wl + X@Wr ) -----------
__global__ __launch_bounds__(256) void k_itemupd(
    const float* __restrict__ srcFeat,
    const int* __restrict__ off, const int* __restrict__ csr,
    const float* __restrict__ Wl,
    const float* __restrict__ X, const float* __restrict__ Wr,
    const float* __restrict__ bias, int relu, float* __restrict__ Y)
{
    __shared__ float4 Xs[2048];
    __shared__ float4 Ws[1024];
    const int tid = threadIdx.x;
    const int tx  = (tid >> 2) & 7;
    const int ty  = (tid >> 5) * 4 + (tid & 3);

    for (int tile = blockIdx.x * 128; tile < NI; tile += gridDim.x * 128) {
        // ---- phase A: gather-mean src rows into Xs ----
        __syncthreads();
        #pragma unroll 1
        for (int i = 0; i < 4; i++) {
            const int r  = ty + 32 * i;
            const int rg = tile + r;
            float a[8];
            #pragma unroll
            for (int t = 0; t < 8; t++) a[t] = 0.f;
            if (rg < NI) {
                int p0 = off[rg], p1 = off[rg + 1];
                int sn = (p0 < p1) ? csr[p0] : 0;
                for (int p = p0; p < p1; p++) {
                    int s = sn;
                    if (p + 1 < p1) sn = csr[p + 1];
                    const float4* fp = reinterpret_cast<const float4*>(srcFeat + s * 64 + tx * 8);
                    float4 v0 = fp[0], v1 = fp[1];
                    a[0] += v0.x; a[1] += v0.y; a[2] += v0.z; a[3] += v0.w;
                    a[4] += v1.x; a[5] += v1.y; a[6] += v1.z; a[7] += v1.w;
                }
                float rc = 1.f / fmaxf((float)(p1 - p0), 1.f);
                #pragma unroll
                for (int t = 0; t < 8; t++) a[t] *= rc;
            }
            Xs[r * 16 + ((tx * 2)     ^ (r & 15))] = make_float4(a[0], a[1], a[2], a[3]);
            Xs[r * 16 + ((tx * 2 + 1) ^ (r & 15))] = make_float4(a[4], a[5], a[6], a[7]);
        }
        #pragma unroll
        for (int j = 0; j < 4; j++) Ws[tid + j * 256] = reinterpret_cast<const float4*>(Wl)[tid + j * 256];
        __syncthreads();

        unsigned long long acc[4][4];
        {
            const float* bp = bias + tx * 8;
            unsigned long long b0 = pk2(bp[0], bp[1]), b1 = pk2(bp[2], bp[3]);
            unsigned long long b2 = pk2(bp[4], bp[5]), b3 = pk2(bp[6], bp[7]);
            #pragma unroll
            for (int i = 0; i < 4; i++) {
                acc[i][0] = b0; acc[i][1] = b1; acc[i][2] = b2; acc[i][3] = b3;
            }
        }
        GEMM_PASS(acc)

        // ---- phase B: X @ Wr ----
        __syncthreads();
        #pragma unroll
        for (int j = 0; j < 8; j++) {
            int f = tid + j * 256;
            int row = f >> 4, c4 = f & 15;
            int rg = tile + row;
            float4 v = make_float4(0.f, 0.f, 0.f, 0.f);
            if (rg < NI) v = reinterpret_cast<const float4*>(X)[rg * 16 + c4];
            Xs[row * 16 + (c4 ^ (row & 15))] = v;
        }
        #pragma unroll
        for (int j = 0; j < 4; j++) Ws[tid + j * 256] = reinterpret_cast<const float4*>(Wr)[tid + j * 256];
        __syncthreads();
        GEMM_PASS(acc)

        // ---- store ----
        #pragma unroll
        for (int i = 0; i < 4; i++) {
            int rg = tile + ty + 32 * i;
            if (rg < NI) {
                float2 r0 = upk(acc[i][0]), r1 = upk(acc[i][1]);
                float2 r2 = upk(acc[i][2]), r3 = upk(acc[i][3]);
                float y[8] = { r0.x, r0.y, r1.x, r1.y, r2.x, r2.y, r3.x, r3.y };
                if (relu) {
                    #pragma unroll
                    for (int t = 0; t < 8; t++) y[t] = fmaxf(y[t], 0.f);
                }
                float4* yp = reinterpret_cast<float4*>(Y + rg * 64 + tx * 8);
                yp[0] = make_float4(y[0], y[1], y[2], y[3]);
                yp[1] = make_float4(y[4], y[5], y[6], y[7]);
            }
        }
    }
}

// ---------------- user update: Y = relu?( b + gathermean(xiT) + X@Wr ) ------------------
__global__ __launch_bounds__(256) void k_userupd(
    const float* __restrict__ xiT,
    const int* __restrict__ off, const int* __restrict__ csr,
    const float* __restrict__ X, const float* __restrict__ Wr,
    const float* __restrict__ bias, int relu, float* __restrict__ Y)
{
    __shared__ float4 Xs[2048];
    __shared__ float4 Ws[1024];
    const int tid = threadIdx.x;
    const int tx  = (tid >> 2) & 7;
    const int ty  = (tid >> 5) * 4 + (tid & 3);

    #pragma unroll
    for (int j = 0; j < 4; j++) Ws[tid + j * 256] = reinterpret_cast<const float4*>(Wr)[tid + j * 256];

    for (int tile = blockIdx.x * 128; tile < NU; tile += gridDim.x * 128) {
        __syncthreads();
        #pragma unroll
        for (int j = 0; j < 8; j++) {
            int f = tid + j * 256;
            int row = f >> 4, c4 = f & 15;
            int rg = tile + row;
            float4 v = make_float4(0.f, 0.f, 0.f, 0.f);
            if (rg < NU) v = reinterpret_cast<const float4*>(X)[rg * 16 + c4];
            Xs[row * 16 + (c4 ^ (row & 15))] = v;
        }
        __syncthreads();

        unsigned long long acc[4][4];
        #pragma unroll 1
        for (int i = 0; i < 4; i++) {
            const int rg = tile + ty + 32 * i;
            float a[8];
            {
                const float* bp = bias + tx * 8;
                #pragma unroll
                for (int t = 0; t < 8; t++) a[t] = bp[t];
            }
            if (rg < NU) {
                int p0 = off[rg], p1 = off[rg + 1];
                float s0 = 0.f, s1 = 0.f, s2 = 0.f, s3 = 0.f,
                      s4 = 0.f, s5 = 0.f, s6 = 0.f, s7 = 0.f;
                int sn = (p0 < p1) ? csr[p0] : 0;
                for (int p = p0; p < p1; p++) {
                    int s = sn;
                    if (p + 1 < p1) sn = csr[p + 1];
                    const float4* fp = reinterpret_cast<const float4*>(xiT + s * 64 + tx * 8);
                    float4 v0 = fp[0], v1 = fp[1];
                    s0 += v0.x; s1 += v0.y; s2 += v0.z; s3 += v0.w;
                    s4 += v1.x; s5 += v1.y; s6 += v1.z; s7 += v1.w;
                }
                float rc = 1.f / fmaxf((float)(p1 - p0), 1.f);
                a[0] += rc * s0; a[1] += rc * s1; a[2] += rc * s2; a[3] += rc * s3;
                a[4] += rc * s4; a[5] += rc * s5; a[6] += rc * s6; a[7] += rc * s7;
            }
            acc[i][0] = pk2(a[0], a[1]); acc[i][1] = pk2(a[2], a[3]);
            acc[i][2] = pk2(a[4], a[5]); acc[i][3] = pk2(a[6], a[7]);
        }

        GEMM_PASS(acc)

        #pragma unroll
        for (int i = 0; i < 4; i++) {
            int rg = tile + ty + 32 * i;
            if (rg < NU) {
                float2 r0 = upk(acc[i][0]), r1 = upk(acc[i][1]);
                float2 r2 = upk(acc[i][2]), r3 = upk(acc[i][3]);
                float y[8] = { r0.x, r0.y, r1.x, r1.y, r2.x, r2.y, r3.x, r3.y };
                if (relu) {
                    #pragma unroll
                    for (int t = 0; t < 8; t++) y[t] = fmaxf(y[t], 0.f);
                }
                float4* yp = reinterpret_cast<float4*>(Y + rg * 64 + tx * 8);
                yp[0] = make_float4(y[0], y[1], y[2], y[3]);
                yp[1] = make_float4(y[4], y[5], y[6], y[7]);
            }
        }
    }
}

// ---------------- item input linear ----------------
__global__ __launch_bounds__(256) void k_lin(
    const float* __restrict__ X, const float* __restrict__ W,
    const float* __restrict__ bias, float* __restrict__ Y)
{
    __shared__ float4 Xs[2048];
    __shared__ float4 Ws[1024];
    const int tid = threadIdx.x;
    const int tx  = (tid >> 2) & 7;
    const int ty  = (tid >> 5) * 4 + (tid & 3);

    for (int tile = blockIdx.x * 128; tile < NI; tile += gridDim.x * 128) {
        unsigned long long acc[4][4];
        {
            const float* bp = bias + tx * 8;
            unsigned long long b0 = pk2(bp[0], bp[1]), b1 = pk2(bp[2], bp[3]);
            unsigned long long b2 = pk2(bp[4], bp[5]), b3 = pk2(bp[6], bp[7]);
            #pragma unroll
            for (int i = 0; i < 4; i++) {
                acc[i][0] = b0; acc[i][1] = b1; acc[i][2] = b2; acc[i][3] = b3;
            }
        }

        #pragma unroll 1
        for (int kc = 0; kc < 5; kc++) {
            const int k0 = kc * 64;
            const int kn = (k0 + 64 <= F) ? 64 : (F - k0);

            __syncthreads();
            #pragma unroll
            for (int j = 0; j < 4; j++) {
                int f = tid + j * 256;
                int k = f >> 4, c4 = f & 15;
                float4 v = make_float4(0.f, 0.f, 0.f, 0.f);
                if (k < kn) v = reinterpret_cast<const float4*>(W + (k0 + k) * 64)[c4];
                Ws[f] = v;
            }
            #pragma unroll
            for (int j = 0; j < 8; j++) {
                int f = tid + j * 256;
                int row = f >> 4, c4 = f & 15;
                int rg = tile + row;
                float4 v = make_float4(0.f, 0.f, 0.f, 0.f);
                if (rg < NI && c4 * 4 < kn)
                    v = *reinterpret_cast<const float4*>(X + rg * F + k0 + c4 * 4);
                Xs[row * 16 + (c4 ^ (row & 15))] = v;
            }
            __syncthreads();
            GEMM_PASS(acc)
        }

        #pragma unroll
        for (int i = 0; i < 4; i++) {
            int rg = tile + ty + 32 * i;
            if (rg < NI) {
                float2 r0 = upk(acc[i][0]), r1 = upk(acc[i][1]);
                float2 r2 = upk(acc[i][2]), r3 = upk(acc[i][3]);
                float4* yp = reinterpret_cast<float4*>(Y + rg * 64 + tx * 8);
                yp[0] = make_float4(r0.x, r0.y, r1.x, r1.y);
                yp[1] = make_float4(r2.x, r2.y, r3.x, r3.y);
            }
        }
    }
}

// ---------------- predictor ----------------
__global__ void k_dot(const float* __restrict__ hu, const float* __restrict__ hi,
                      const int* __restrict__ ls, const int* __restrict__ ld,
                      float* __restrict__ out) {
    int i = blockIdx.x * blockDim.x + threadIdx.x;
    int e = i >> 3;
    int j = i & 7;
    if (e >= EL) return;
    int u = ls[e];
    int v = ld[e];
    const float4* pa = reinterpret_cast<const float4*>(hu + u * 64 + j * 8);
    const float4* pb = reinterpret_cast<const float4*>(hi + v * 64 + j * 8);
    float4 a0 = pa[0], a1 = pa[1], b0 = pb[0], b1 = pb[1];
    float s = a0.x * b0.x + a0.y * b0.y + a0.z * b0.z + a0.w * b0.w
            + a1.x * b1.x + a1.y * b1.y + a1.z * b1.z + a1.w * b1.w;
    s += __shfl_down_sync(0xffffffffu, s, 4, 8);
    s += __shfl_down_sync(0xffffffffu, s, 2, 8);
    s += __shfl_down_sync(0xffffffffu, s, 1, 8);
    if (j == 0) out[e] = s;
}

// ---------------- launch ----------------
extern "C" void kernel_launch(void* const* d_in, const int* in_sizes, int n_in,
                              void* d_out, int out_size) {
    const float* user_emb = (const float*)d_in[0];
    const float* item_x   = (const float*)d_in[1];
    const float* Wlin     = (const float*)d_in[2];
    const float* blin     = (const float*)d_in[3];
    const float* Wl1_ui   = (const float*)d_in[4];
    const float* Wr1_ui   = (const float*)d_in[5];
    const float* b1_ui    = (const float*)d_in[6];
    const float* Wl1_iu   = (const float*)d_in[7];
    const float* Wr1_iu   = (const float*)d_in[8];
    const float* b1_iu    = (const float*)d_in[9];
    const float* Wl2_ui   = (const float*)d_in[10];
    const float* Wr2_ui   = (const float*)d_in[11];
    const float* b2_ui    = (const float*)d_in[12];
    const float* Wl2_iu   = (const float*)d_in[13];
    const float* Wr2_iu   = (const float*)d_in[14];
    const float* b2_iu    = (const float*)d_in[15];
    const int* es   = (const int*)d_in[17];
    const int* ed   = (const int*)d_in[18];
    const int* ls   = (const int*)d_in[19];
    const int* ldst = (const int*)d_in[20];
    float* out = (float*)d_out;

    float *xi, *xiT, *hu, *hi;
    int *degI, *degU, *offI, *offU, *csrI, *csrU, *bsI, *bsU;
    cudaGetSymbolAddress((void**)&xi,   g_xi);
    cudaGetSymbolAddress((void**)&xiT,  g_xiT);
    cudaGetSymbolAddress((void**)&hu,   g_hu);
    cudaGetSymbolAddress((void**)&hi,   g_hi);
    cudaGetSymbolAddress((void**)&degI, g_degI);
    cudaGetSymbolAddress((void**)&degU, g_degU);
    cudaGetSymbolAddress((void**)&offI, g_offI);
    cudaGetSymbolAddress((void**)&offU, g_offU);
    cudaGetSymbolAddress((void**)&csrI, g_csrI);
    cudaGetSymbolAddress((void**)&csrU, g_csrU);
    cudaGetSymbolAddress((void**)&bsI,  g_bsumI);
    cudaGetSymbolAddress((void**)&bsU,  g_bsumU);

    const int GMM = 444;
    const int nbI = (NI + 2047) / 2048;   // 49
    const int nbU = (NU + 2047) / 2048;   // 245

    // ---- CSR build ----
    k_zero_deg<<<(NU + 255) / 256, 256>>>();
    k_count<<<(E + 255) / 256, 256>>>(es, ed);
    k_scan_a<<<nbI, 256>>>(degI, NI, offI, bsI);
    k_scan_b<<<1, 256>>>(bsI, nbI);
    k_scan_c<<<(NI + 255) / 256, 256>>>(offI, bsI, NI, E);
    k_scan_a<<<nbU, 256>>>(degU, NU, offU, bsU);
    k_scan_b<<<1, 256>>>(bsU, nbU);
    k_scan_c<<<(NU + 255) / 256, 256>>>(offU, bsU, NU, E);
    k_fill<<<(E + 255) / 256, 256>>>(es, ed);

    // ---- item input linear ----
    k_lin<<<GMM, 256>>>(item_x, Wlin, blin, xi);

    // ---- layer 1 ----
    k_gemm<<<GMM, 256>>>(xi, Wl1_iu, xiT, NI);
    k_itemupd<<<GMM, 256>>>(user_emb, offI, csrI, Wl1_ui, xi, Wr1_ui, b1_ui, 1, hi);
    k_userupd<<<GMM, 256>>>(xiT, offU, csrU, user_emb, Wr1_iu, b1_iu, 1, hu);

    // ---- layer 2 ----
    k_gemm<<<GMM, 256>>>(hi, Wl2_iu, xiT, NI);
    k_itemupd<<<GMM, 256>>>(hu, offI, csrI, Wl2_ui, hi, Wr2_ui, b2_ui, 0, hi);
    k_userupd<<<GMM, 256>>>(xiT, offU, csrU, hu, Wr2_iu, b2_iu, 0, hu);

    // ---- predictor ----
    k_dot<<<(EL * 8) / 256, 256>>>(hu, hi, ls, ldst, out);
}

// round 4
// speedup vs baseline: 3.7317x; 1.2226x over previous
#include <cuda_runtime.h>

static constexpr int NU = 500000;
static constexpr int NI = 100000;
static constexpr int F  = 300;
static constexpr int D  = 64;
static constexpr int E  = 2000000;
static constexpr int EL = 1000000;

// grid constants
static constexpr int TILES_I = (NI + 127) / 128;   // 782
static constexpr int TILES_U = (NU + 127) / 128;   // 3907
static constexpr int EBLK    = (E + 255) / 256;    // 7813

// ---------------- device scratch ----------------
__device__ float g_xi  [NI * D];
__device__ float g_xiT [NI * D];
__device__ float g_hi  [NI * D];
__device__ float g_hi2 [NI * D];
__device__ float g_hu  [NU * D];
__device__ float g_hu2 [NU * D];
__device__ int   g_degI[NI];
__device__ int   g_degU[NU];
__device__ int   g_offI[NI + 1];
__device__ int   g_offU[NU + 1];
__device__ int   g_curI[NI];
__device__ int   g_curU[NU];
__device__ int   g_csrI[E];
__device__ int   g_csrU[E];
__device__ int   g_bsumI[64];
__device__ int   g_bsumU[256];

// ---------------- helpers ----------------
__device__ __forceinline__ unsigned long long pk2(float a, float b) {
    float2 t = make_float2(a, b);
    return *reinterpret_cast<unsigned long long*>(&t);
}
__device__ __forceinline__ float2 upk(unsigned long long v) {
    return *reinterpret_cast<float2*>(&v);
}
__device__ __forceinline__ unsigned long long ffma2(unsigned long long a,
                                                    unsigned long long b,
                                                    unsigned long long c) {
    unsigned long long d;
    asm("fma.rn.f32x2 %0, %1, %2, %3;" : "=l"(d) : "l"(a), "l"(b), "l"(c));
    return d;
}

// ---------------- GEMM inner pass (tile 128x64, 256 thr, 4x8 per thread) ----------------
#define GEMM_PASS(ACC)                                                            \
    _Pragma("unroll")                                                             \
    for (int kb = 0; kb < 16; kb++) {                                             \
        float4 xv[4];                                                             \
        _Pragma("unroll")                                                         \
        for (int i = 0; i < 4; i++) {                                             \
            int r = ty + 32 * i;                                                  \
            xv[i] = Xs[r * 16 + (kb ^ (r & 15))];                                 \
        }                                                                         \
        _Pragma("unroll")                                                         \
        for (int q = 0; q < 4; q++) {                                             \
            int k = kb * 4 + q;                                                   \
            ulonglong2 wA = *reinterpret_cast<const ulonglong2*>(Ws + k * 16 + tx * 2);     \
            ulonglong2 wB = *reinterpret_cast<const ulonglong2*>(Ws + k * 16 + tx * 2 + 1); \
            _Pragma("unroll")                                                     \
            for (int i = 0; i < 4; i++) {                                         \
                float a = (q == 0) ? xv[i].x : (q == 1) ? xv[i].y                 \
                        : (q == 2) ? xv[i].z : xv[i].w;                           \
                unsigned long long a2 = pk2(a, a);                                \
                ACC[i][0] = ffma2(a2, wA.x, ACC[i][0]);                           \
                ACC[i][1] = ffma2(a2, wA.y, ACC[i][1]);                           \
                ACC[i][2] = ffma2(a2, wB.x, ACC[i][2]);                           \
                ACC[i][3] = ffma2(a2, wB.y, ACC[i][3]);                           \
            }                                                                     \
        }                                                                         \
    }

// ---------------- CSR build pieces ----------------
__global__ void k_zero_deg() {
    int i = blockIdx.x * blockDim.x + threadIdx.x;
    if (i < NU) { g_degU[i] = 0; g_curU[i] = 0; }
    if (i < NI) { g_degI[i] = 0; g_curI[i] = 0; }
}
__global__ void k_scan_a(const int* __restrict__ deg, int n,
                         int* __restrict__ out, int* __restrict__ bsum) {
    __shared__ int ws[8];
    const int t = threadIdx.x;
    const int base = blockIdx.x * 2048 + t * 8;
    int v[8];
    #pragma unroll
    for (int j = 0; j < 8; j++) v[j] = (base + j < n) ? deg[base + j] : 0;
    int s = 0;
    #pragma unroll
    for (int j = 0; j < 8; j++) { int x = v[j]; v[j] = s; s += x; }
    const int lane = t & 31, wid = t >> 5;
    int sx = s;
    #pragma unroll
    for (int o = 1; o < 32; o <<= 1) {
        int y = __shfl_up_sync(0xffffffffu, sx, o);
        if (lane >= o) sx += y;
    }
    if (lane == 31) ws[wid] = sx;
    __syncthreads();
    if (wid == 0 && lane < 8) {
        int b = ws[lane];
        int bx = b;
        #pragma unroll
        for (int o = 1; o < 8; o <<= 1) {
            int y = __shfl_up_sync(0xffu, bx, o);
            if (lane >= o) bx += y;
        }
        ws[lane] = bx - b;
        if (lane == 7) bsum[blockIdx.x] = bx;
    }
    __syncthreads();
    const int off = ws[wid] + (sx - s);
    #pragma unroll
    for (int j = 0; j < 8; j++)
        if (base + j < n) out[base + j] = off + v[j];
}
__global__ void k_scan_b(int* __restrict__ bsum, int nb) {
    __shared__ int sm[256];
    const int t = threadIdx.x;
    int v = (t < nb) ? bsum[t] : 0;
    sm[t] = v;
    __syncthreads();
    for (int o = 1; o < 256; o <<= 1) {
        int y = (t >= o) ? sm[t - o] : 0;
        __syncthreads();
        sm[t] += y;
        __syncthreads();
    }
    if (t < nb) bsum[t] = sm[t] - v;
}
__global__ void k_scan_c(int* __restrict__ out, const int* __restrict__ bsum,
                         int n, int total) {
    int i = blockIdx.x * blockDim.x + threadIdx.x;
    if (i < n) out[i] += bsum[i >> 11];
    if (i == 0) out[n] = total;
}

// ============================================================================
// fused: item input linear (blocks < TILES_I) || degree count (rest)
// ============================================================================
__global__ __launch_bounds__(256) void k_lin_count(
    const float* __restrict__ X, const float* __restrict__ W,
    const float* __restrict__ bias, float* __restrict__ Y,
    const int* __restrict__ es, const int* __restrict__ ed)
{
    if (blockIdx.x >= TILES_I) {
        int i = (int)(blockIdx.x - TILES_I) * 256 + threadIdx.x;
        if (i < E) {
            atomicAdd(&g_degU[es[i]], 1);
            atomicAdd(&g_degI[ed[i]], 1);
        }
        return;
    }
    __shared__ float4 Xs[2048];
    __shared__ float4 Ws[1024];
    const int tid = threadIdx.x;
    const int tx  = (tid >> 2) & 7;
    const int ty  = (tid >> 5) * 4 + (tid & 3);
    const int tile = blockIdx.x * 128;

    unsigned long long acc[4][4];
    {
        const float* bp = bias + tx * 8;
        unsigned long long b0 = pk2(bp[0], bp[1]), b1 = pk2(bp[2], bp[3]);
        unsigned long long b2 = pk2(bp[4], bp[5]), b3 = pk2(bp[6], bp[7]);
        #pragma unroll
        for (int i = 0; i < 4; i++) {
            acc[i][0] = b0; acc[i][1] = b1; acc[i][2] = b2; acc[i][3] = b3;
        }
    }

    #pragma unroll 1
    for (int kc = 0; kc < 5; kc++) {
        const int k0 = kc * 64;
        const int kn = (k0 + 64 <= F) ? 64 : (F - k0);

        __syncthreads();
        #pragma unroll
        for (int j = 0; j < 4; j++) {
            int f = tid + j * 256;
            int k = f >> 4, c4 = f & 15;
            float4 v = make_float4(0.f, 0.f, 0.f, 0.f);
            if (k < kn) v = reinterpret_cast<const float4*>(W + (k0 + k) * 64)[c4];
            Ws[f] = v;
        }
        #pragma unroll
        for (int j = 0; j < 8; j++) {
            int f = tid + j * 256;
            int row = f >> 4, c4 = f & 15;
            int rg = tile + row;
            float4 v = make_float4(0.f, 0.f, 0.f, 0.f);
            if (rg < NI && c4 * 4 < kn)
                v = *reinterpret_cast<const float4*>(X + rg * F + k0 + c4 * 4);
            Xs[row * 16 + (c4 ^ (row & 15))] = v;
        }
        __syncthreads();
        GEMM_PASS(acc)
    }

    #pragma unroll
    for (int i = 0; i < 4; i++) {
        int rg = tile + ty + 32 * i;
        if (rg < NI) {
            float2 r0 = upk(acc[i][0]), r1 = upk(acc[i][1]);
            float2 r2 = upk(acc[i][2]), r3 = upk(acc[i][3]);
            float4* yp = reinterpret_cast<float4*>(Y + rg * 64 + tx * 8);
            yp[0] = make_float4(r0.x, r0.y, r1.x, r1.y);
            yp[1] = make_float4(r2.x, r2.y, r3.x, r3.y);
        }
    }
}

// ---------------- plain GEMM tile body (Y = X @ W, N rows) ----------------
__device__ __forceinline__ void gemm_tile(
    int tile, const float* __restrict__ X, const float* __restrict__ W,
    float* __restrict__ Y, int N, float4* Xs, float4* Ws)
{
    const int tid = threadIdx.x;
    const int tx  = (tid >> 2) & 7;
    const int ty  = (tid >> 5) * 4 + (tid & 3);

    #pragma unroll
    for (int j = 0; j < 4; j++)
        Ws[tid + j * 256] = reinterpret_cast<const float4*>(W)[tid + j * 256];
    #pragma unroll
    for (int j = 0; j < 8; j++) {
        int f = tid + j * 256;
        int row = f >> 4, c4 = f & 15;
        int rg = tile + row;
        float4 v = make_float4(0.f, 0.f, 0.f, 0.f);
        if (rg < N) v = reinterpret_cast<const float4*>(X)[rg * 16 + c4];
        Xs[row * 16 + (c4 ^ (row & 15))] = v;
    }
    __syncthreads();

    unsigned long long acc[4][4];
    #pragma unroll
    for (int i = 0; i < 4; i++)
        #pragma unroll
        for (int t = 0; t < 4; t++) acc[i][t] = 0ull;

    GEMM_PASS(acc)

    #pragma unroll
    for (int i = 0; i < 4; i++) {
        int rg = tile + ty + 32 * i;
        if (rg < N) {
            float2 r0 = upk(acc[i][0]), r1 = upk(acc[i][1]);
            float2 r2 = upk(acc[i][2]), r3 = upk(acc[i][3]);
            float4* yp = reinterpret_cast<float4*>(Y + rg * 64 + tx * 8);
            yp[0] = make_float4(r0.x, r0.y, r1.x, r1.y);
            yp[1] = make_float4(r2.x, r2.y, r3.x, r3.y);
        }
    }
}

// ============================================================================
// fused: gemm (xiT = xi @ Wl_iu) || csr fill
// ============================================================================
__global__ __launch_bounds__(256) void k_gemm_fill(
    const float* __restrict__ X, const float* __restrict__ W, float* __restrict__ Y,
    const int* __restrict__ es, const int* __restrict__ ed)
{
    if (blockIdx.x >= TILES_I) {
        int e = (int)(blockIdx.x - TILES_I) * 256 + threadIdx.x;
        if (e < E) {
            int u = es[e], it = ed[e];
            g_csrI[g_offI[it] + atomicAdd(&g_curI[it], 1)] = u;
            g_csrU[g_offU[u] + atomicAdd(&g_curU[u], 1)] = it;
        }
        return;
    }
    __shared__ float4 Xs[2048];
    __shared__ float4 Ws[1024];
    gemm_tile(blockIdx.x * 128, X, W, Y, NI, Xs, Ws);
}

// plain gemm launch (layer 2 pre-transform)
__global__ __launch_bounds__(256) void k_gemm(
    const float* __restrict__ X, const float* __restrict__ W, float* __restrict__ Y, int N)
{
    __shared__ float4 Xs[2048];
    __shared__ float4 Ws[1024];
    gemm_tile(blockIdx.x * 128, X, W, Y, N, Xs, Ws);
}

// ============================================================================
// fused node update: item tiles (blocks < TILES_I) || user tiles (rest)
// ============================================================================
__device__ __forceinline__ void item_tile(
    int tile,
    const float* __restrict__ srcFeat,
    const int* __restrict__ off, const int* __restrict__ csr,
    const float* __restrict__ Wl,
    const float* __restrict__ X, const float* __restrict__ Wr,
    const float* __restrict__ bias, int relu, float* __restrict__ Y,
    float4* Xs, float4* Ws)
{
    const int tid = threadIdx.x;
    const int tx  = (tid >> 2) & 7;
    const int ty  = (tid >> 5) * 4 + (tid & 3);

    // phase A: gather-mean src rows into Xs (2-edge unrolled)
    #pragma unroll 1
    for (int i = 0; i < 4; i++) {
        const int r  = ty + 32 * i;
        const int rg = tile + r;
        float a[8];
        #pragma unroll
        for (int t = 0; t < 8; t++) a[t] = 0.f;
        if (rg < NI) {
            int p0 = off[rg], p1 = off[rg + 1];
            int p = p0;
            for (; p + 2 <= p1; p += 2) {
                int sA = csr[p], sB = csr[p + 1];
                const float4* fA = reinterpret_cast<const float4*>(srcFeat + sA * 64 + tx * 8);
                const float4* fB = reinterpret_cast<const float4*>(srcFeat + sB * 64 + tx * 8);
                float4 a0 = fA[0], a1 = fA[1], b0 = fB[0], b1 = fB[1];
                a[0] += a0.x + b0.x; a[1] += a0.y + b0.y;
                a[2] += a0.z + b0.z; a[3] += a0.w + b0.w;
                a[4] += a1.x + b1.x; a[5] += a1.y + b1.y;
                a[6] += a1.z + b1.z; a[7] += a1.w + b1.w;
            }
            if (p < p1) {
                int s = csr[p];
                const float4* fp = reinterpret_cast<const float4*>(srcFeat + s * 64 + tx * 8);
                float4 v0 = fp[0], v1 = fp[1];
                a[0] += v0.x; a[1] += v0.y; a[2] += v0.z; a[3] += v0.w;
                a[4] += v1.x; a[5] += v1.y; a[6] += v1.z; a[7] += v1.w;
            }
            float rc = 1.f / fmaxf((float)(p1 - p0), 1.f);
            #pragma unroll
            for (int t = 0; t < 8; t++) a[t] *= rc;
        }
        Xs[r * 16 + ((tx * 2)     ^ (r & 15))] = make_float4(a[0], a[1], a[2], a[3]);
        Xs[r * 16 + ((tx * 2 + 1) ^ (r & 15))] = make_float4(a[4], a[5], a[6], a[7]);
    }
    #pragma unroll
    for (int j = 0; j < 4; j++)
        Ws[tid + j * 256] = reinterpret_cast<const float4*>(Wl)[tid + j * 256];
    __syncthreads();

    unsigned long long acc[4][4];
    {
        const float* bp = bias + tx * 8;
        unsigned long long b0 = pk2(bp[0], bp[1]), b1 = pk2(bp[2], bp[3]);
        unsigned long long b2 = pk2(bp[4], bp[5]), b3 = pk2(bp[6], bp[7]);
        #pragma unroll
        for (int i = 0; i < 4; i++) {
            acc[i][0] = b0; acc[i][1] = b1; acc[i][2] = b2; acc[i][3] = b3;
        }
    }
    GEMM_PASS(acc)

    // phase B: X @ Wr
    __syncthreads();
    #pragma unroll
    for (int j = 0; j < 8; j++) {
        int f = tid + j * 256;
        int row = f >> 4, c4 = f & 15;
        int rg = tile + row;
        float4 v = make_float4(0.f, 0.f, 0.f, 0.f);
        if (rg < NI) v = reinterpret_cast<const float4*>(X)[rg * 16 + c4];
        Xs[row * 16 + (c4 ^ (row & 15))] = v;
    }
    #pragma unroll
    for (int j = 0; j < 4; j++)
        Ws[tid + j * 256] = reinterpret_cast<const float4*>(Wr)[tid + j * 256];
    __syncthreads();
    GEMM_PASS(acc)

    #pragma unroll
    for (int i = 0; i < 4; i++) {
        int rg = tile + ty + 32 * i;
        if (rg < NI) {
            float2 r0 = upk(acc[i][0]), r1 = upk(acc[i][1]);
            float2 r2 = upk(acc[i][2]), r3 = upk(acc[i][3]);
            float y[8] = { r0.x, r0.y, r1.x, r1.y, r2.x, r2.y, r3.x, r3.y };
            if (relu) {
                #pragma unroll
                for (int t = 0; t < 8; t++) y[t] = fmaxf(y[t], 0.f);
            }
            float4* yp = reinterpret_cast<float4*>(Y + rg * 64 + tx * 8);
            yp[0] = make_float4(y[0], y[1], y[2], y[3]);
            yp[1] = make_float4(y[4], y[5], y[6], y[7]);
        }
    }
}

__device__ __forceinline__ void user_tile(
    int tile,
    const float* __restrict__ gsrc,     // xiT (pre-transformed item feats)
    const int* __restrict__ off, const int* __restrict__ csr,
    const float* __restrict__ X, const float* __restrict__ Wr,
    const float* __restrict__ bias, int relu, float* __restrict__ Y,
    float4* Xs, float4* Ws)
{
    const int tid = threadIdx.x;
    const int tx  = (tid >> 2) & 7;
    const int ty  = (tid >> 5) * 4 + (tid & 3);

    #pragma unroll
    for (int j = 0; j < 4; j++)
        Ws[tid + j * 256] = reinterpret_cast<const float4*>(Wr)[tid + j * 256];
    #pragma unroll
    for (int j = 0; j < 8; j++) {
        int f = tid + j * 256;
        int row = f >> 4, c4 = f & 15;
        int rg = tile + row;
        float4 v = make_float4(0.f, 0.f, 0.f, 0.f);
        if (rg < NU) v = reinterpret_cast<const float4*>(X)[rg * 16 + c4];
        Xs[row * 16 + (c4 ^ (row & 15))] = v;
    }
    __syncthreads();

    unsigned long long acc[4][4];
    #pragma unroll 1
    for (int i = 0; i < 4; i++) {
        const int rg = tile + ty + 32 * i;
        float a[8];
        {
            const float* bp = bias + tx * 8;
            #pragma unroll
            for (int t = 0; t < 8; t++) a[t] = bp[t];
        }
        if (rg < NU) {
            int p0 = off[rg], p1 = off[rg + 1];
            float s[8];
            #pragma unroll
            for (int t = 0; t < 8; t++) s[t] = 0.f;
            int p = p0;
            for (; p + 2 <= p1; p += 2) {
                int sA = csr[p], sB = csr[p + 1];
                const float4* fA = reinterpret_cast<const float4*>(gsrc + sA * 64 + tx * 8);
                const float4* fB = reinterpret_cast<const float4*>(gsrc + sB * 64 + tx * 8);
                float4 a0 = fA[0], a1 = fA[1], b0 = fB[0], b1 = fB[1];
                s[0] += a0.x + b0.x; s[1] += a0.y + b0.y;
                s[2] += a0.z + b0.z; s[3] += a0.w + b0.w;
                s[4] += a1.x + b1.x; s[5] += a1.y + b1.y;
                s[6] += a1.z + b1.z; s[7] += a1.w + b1.w;
            }
            if (p < p1) {
                int sI = csr[p];
                const float4* fp = reinterpret_cast<const float4*>(gsrc + sI * 64 + tx * 8);
                float4 v0 = fp[0], v1 = fp[1];
                s[0] += v0.x; s[1] += v0.y; s[2] += v0.z; s[3] += v0.w;
                s[4] += v1.x; s[5] += v1.y; s[6] += v1.z; s[7] += v1.w;
            }
            float rc = 1.f / fmaxf((float)(p1 - p0), 1.f);
            #pragma unroll
            for (int t = 0; t < 8; t++) a[t] += rc * s[t];
        }
        acc[i][0] = pk2(a[0], a[1]); acc[i][1] = pk2(a[2], a[3]);
        acc[i][2] = pk2(a[4], a[5]); acc[i][3] = pk2(a[6], a[7]);
    }

    GEMM_PASS(acc)

    #pragma unroll
    for (int i = 0; i < 4; i++) {
        int rg = tile + ty + 32 * i;
        if (rg < NU) {
            float2 r0 = upk(acc[i][0]), r1 = upk(acc[i][1]);
            float2 r2 = upk(acc[i][2]), r3 = upk(acc[i][3]);
            float y[8] = { r0.x, r0.y, r1.x, r1.y, r2.x, r2.y, r3.x, r3.y };
            if (relu) {
                #pragma unroll
                for (int t = 0; t < 8; t++) y[t] = fmaxf(y[t], 0.f);
            }
            float4* yp = reinterpret_cast<float4*>(Y + rg * 64 + tx * 8);
            yp[0] = make_float4(y[0], y[1], y[2], y[3]);
            yp[1] = make_float4(y[4], y[5], y[6], y[7]);
        }
    }
}

__global__ __launch_bounds__(256) void k_upd(
    // item side
    const float* __restrict__ itemGsrc, const float* __restrict__ Wl_ui,
    const float* __restrict__ itemX, const float* __restrict__ Wr_ui,
    const float* __restrict__ b_ui, float* __restrict__ Yi,
    // user side
    const float* __restrict__ userGsrc, const float* __restrict__ userX,
    const float* __restrict__ Wr_iu, const float* __restrict__ b_iu,
    float* __restrict__ Yu,
    int relu)
{
    __shared__ float4 Xs[2048];
    __shared__ float4 Ws[1024];
    int *offI, *offU, *csrI, *csrU;
    // device-symbol addresses are directly usable in device code
    offI = g_offI; offU = g_offU; csrI = g_csrI; csrU = g_csrU;

    if (blockIdx.x < TILES_I) {
        item_tile(blockIdx.x * 128, itemGsrc, offI, csrI, Wl_ui, itemX, Wr_ui,
                  b_ui, relu, Yi, Xs, Ws);
    } else {
        user_tile((int)(blockIdx.x - TILES_I) * 128, userGsrc, offU, csrU,
                  userX, Wr_iu, b_iu, relu, Yu, Xs, Ws);
    }
}

// ---------------- predictor ----------------
__global__ void k_dot(const float* __restrict__ hu, const float* __restrict__ hi,
                      const int* __restrict__ ls, const int* __restrict__ ld,
                      float* __restrict__ out) {
    int i = blockIdx.x * blockDim.x + threadIdx.x;
    int e = i >> 3;
    int j = i & 7;
    if (e >= EL) return;
    int u = ls[e];
    int v = ld[e];
    const float4* pa = reinterpret_cast<const float4*>(hu + u * 64 + j * 8);
    const float4* pb = reinterpret_cast<const float4*>(hi + v * 64 + j * 8);
    float4 a0 = pa[0], a1 = pa[1], b0 = pb[0], b1 = pb[1];
    float s = a0.x * b0.x + a0.y * b0.y + a0.z * b0.z + a0.w * b0.w
            + a1.x * b1.x + a1.y * b1.y + a1.z * b1.z + a1.w * b1.w;
    s += __shfl_down_sync(0xffffffffu, s, 4, 8);
    s += __shfl_down_sync(0xffffffffu, s, 2, 8);
    s += __shfl_down_sync(0xffffffffu, s, 1, 8);
    if (j == 0) out[e] = s;
}

// ---------------- launch ----------------
extern "C" void kernel_launch(void* const* d_in, const int* in_sizes, int n_in,
                              void* d_out, int out_size) {
    const float* user_emb = (const float*)d_in[0];
    const float* item_x   = (const float*)d_in[1];
    const float* Wlin     = (const float*)d_in[2];
    const float* blin     = (const float*)d_in[3];
    const float* Wl1_ui   = (const float*)d_in[4];
    const float* Wr1_ui   = (const float*)d_in[5];
    const float* b1_ui    = (const float*)d_in[6];
    const float* Wl1_iu   = (const float*)d_in[7];
    const float* Wr1_iu   = (const float*)d_in[8];
    const float* b1_iu    = (const float*)d_in[9];
    const float* Wl2_ui   = (const float*)d_in[10];
    const float* Wr2_ui   = (const float*)d_in[11];
    const float* b2_ui    = (const float*)d_in[12];
    const float* Wl2_iu   = (const float*)d_in[13];
    const float* Wr2_iu   = (const float*)d_in[14];
    const float* b2_iu    = (const float*)d_in[15];
    const int* es   = (const int*)d_in[17];
    const int* ed   = (const int*)d_in[18];
    const int* ls   = (const int*)d_in[19];
    const int* ldst = (const int*)d_in[20];
    float* out = (float*)d_out;

    float *xi, *xiT, *hu, *hi, *hu2, *hi2;
    int *degI, *degU, *offI, *offU, *bsI, *bsU;
    cudaGetSymbolAddress((void**)&xi,   g_xi);
    cudaGetSymbolAddress((void**)&xiT,  g_xiT);
    cudaGetSymbolAddress((void**)&hu,   g_hu);
    cudaGetSymbolAddress((void**)&hi,   g_hi);
    cudaGetSymbolAddress((void**)&hu2,  g_hu2);
    cudaGetSymbolAddress((void**)&hi2,  g_hi2);
    cudaGetSymbolAddress((void**)&degI, g_degI);
    cudaGetSymbolAddress((void**)&degU, g_degU);
    cudaGetSymbolAddress((void**)&offI, g_offI);
    cudaGetSymbolAddress((void**)&offU, g_offU);
    cudaGetSymbolAddress((void**)&bsI,  g_bsumI);
    cudaGetSymbolAddress((void**)&bsU,  g_bsumU);

    const int nbI = (NI + 2047) / 2048;   // 49
    const int nbU = (NU + 2047) / 2048;   // 245

    // zero degrees, then fused [item linear || degree count]
    k_zero_deg<<<(NU + 255) / 256, 256>>>();
    k_lin_count<<<TILES_I + EBLK, 256>>>(item_x, Wlin, blin, xi, es, ed);

    // offsets (exclusive scans)
    k_scan_a<<<nbI, 256>>>(degI, NI, offI, bsI);
    k_scan_b<<<1, 256>>>(bsI, nbI);
    k_scan_c<<<(NI + 255) / 256, 256>>>(offI, bsI, NI, E);
    k_scan_a<<<nbU, 256>>>(degU, NU, offU, bsU);
    k_scan_b<<<1, 256>>>(bsU, nbU);
    k_scan_c<<<(NU + 255) / 256, 256>>>(offU, bsU, NU, E);

    // fused [xiT1 = xi @ Wl1_iu || csr fill]
    k_gemm_fill<<<TILES_I + EBLK, 256>>>(xi, Wl1_iu, xiT, es, ed);

    // layer 1 fused [item update || user update]
    k_upd<<<TILES_I + TILES_U, 256>>>(user_emb, Wl1_ui, xi, Wr1_ui, b1_ui, hi,
                                      xiT, user_emb, Wr1_iu, b1_iu, hu, 1);

    // xiT2 = hi @ Wl2_iu
    k_gemm<<<TILES_I, 256>>>(hi, Wl2_iu, xiT, NI);

    // layer 2 fused (ping-pong outputs to decouple from inputs)
    k_upd<<<TILES_I + TILES_U, 256>>>(hu, Wl2_ui, hi, Wr2_ui, b2_ui, hi2,
                                      xiT, hu, Wr2_iu, b2_iu, hu2, 0);

    // predictor
    k_dot<<<(EL * 8) / 256, 256>>>(hu2, hi2, ls, ldst, out);
}